// round 1
// baseline (speedup 1.0000x reference)
#include <cuda_runtime.h>

#define H 512
#define W 512
#define HW (H * W)
#define BN_EPS 1e-5f

// Precomputed effective weights (written by prep_kernel each launch).
__device__ float g_Weff[675];   // [(c*5+u)*5+v]*9+k : scaled 5x5 weights on input
__device__ float g_W0[243];     // [(j*3+u)*3+v]*9+k : scaled 3x3 weights on input0
__device__ float g_Shift[9];    // BN shift per k

// ---------------------------------------------------------------------------
// Kernel 1: fold im2col+conv into effective 5x5 / 3x3 weights, fold BN scale.
// ---------------------------------------------------------------------------
__global__ void prep_kernel(const float* __restrict__ cw,
                            const float* __restrict__ gam,
                            const float* __restrict__ bet,
                            const float* __restrict__ mu,
                            const float* __restrict__ var) {
    int tid = threadIdx.x;
    if (tid < 675) {
        int k = tid % 9;
        int rest = tid / 9;
        int v = rest % 5; rest /= 5;
        int u = rest % 5;
        int c = rest / 5;
        float s = gam[k] * rsqrtf(var[k] + BN_EPS);
        float sum = 0.f;
        for (int ti = 0; ti < 3; ti++) {
            int di = u - ti;
            if (di < 0 || di > 2) continue;
            for (int tj = 0; tj < 3; tj++) {
                int dj = v - tj;
                if (dj < 0 || dj > 2) continue;
                int t = ti * 3 + tj;
                if (c == 0 && t >= 4 && t <= 6) continue;  // replaced rows
                sum += cw[((k * 27 + c * 9 + t) * 3 + di) * 3 + dj];
            }
        }
        g_Weff[tid] = s * sum;
    } else if (tid < 675 + 243) {
        int i = tid - 675;
        int k = i % 9;
        int rest = i / 9;
        int v = rest % 3; rest /= 3;
        int u = rest % 3;
        int j = rest / 3;
        float s = gam[k] * rsqrtf(var[k] + BN_EPS);
        g_W0[i] = s * cw[((k * 27 + 4 + j) * 3 + u) * 3 + v];
    } else if (tid < 675 + 243 + 9) {
        int k = tid - 918;
        float s = gam[k] * rsqrtf(var[k] + BN_EPS);
        g_Shift[k] = bet[k] - mu[k] * s;
    }
}

// ---------------------------------------------------------------------------
// Load 8 consecutive floats [w0-2, w0+5] from a row, with guards.
// ---------------------------------------------------------------------------
__device__ __forceinline__ void load8(const float* __restrict__ rowp, int w0,
                                      bool rowok, bool colsafe, float* v8) {
    if (rowok) {
        if (colsafe) {
            // w0 is a multiple of 4, so w0-2 is even -> 8B-aligned float2 loads.
            float2 a0 = *(const float2*)(rowp + w0 - 2);
            float2 a1 = *(const float2*)(rowp + w0);
            float2 a2 = *(const float2*)(rowp + w0 + 2);
            float2 a3 = *(const float2*)(rowp + w0 + 4);
            v8[0] = a0.x; v8[1] = a0.y; v8[2] = a1.x; v8[3] = a1.y;
            v8[4] = a2.x; v8[5] = a2.y; v8[6] = a3.x; v8[7] = a3.y;
        } else {
#pragma unroll
            for (int i = 0; i < 8; i++) {
                int ww = w0 - 2 + i;
                v8[i] = (ww >= 0 && ww < W) ? rowp[ww] : 0.f;
            }
        }
    } else {
#pragma unroll
        for (int i = 0; i < 8; i++) v8[i] = 0.f;
    }
}

// ---------------------------------------------------------------------------
// Kernel 2: main fused kernel. Block = 8x16 threads, each thread -> 4 pixels
// along w. Tile = 32x16 pixels. Interior formula (exact except 1-px ring).
// ---------------------------------------------------------------------------
__global__ __launch_bounds__(128) void cspn_main(const float* __restrict__ ker,
                                                 const float* __restrict__ in,
                                                 const float* __restrict__ in0,
                                                 float* __restrict__ out) {
    __shared__ float sW[675];
    __shared__ float s0[243];
    __shared__ float sS[9];

    int tid = threadIdx.y * 8 + threadIdx.x;
    for (int i = tid; i < 675; i += 128) sW[i] = g_Weff[i];
    for (int i = tid; i < 243; i += 128) s0[i] = g_W0[i];
    if (tid < 9) sS[tid] = g_Shift[tid];
    __syncthreads();

    const int b  = blockIdx.z;
    const int h  = blockIdx.y * 16 + threadIdx.y;
    const int w0 = blockIdx.x * 32 + threadIdx.x * 4;

    float acc[9][4];
#pragma unroll
    for (int k = 0; k < 9; k++)
#pragma unroll
        for (int p = 0; p < 4; p++) acc[k][p] = 0.f;

    const bool colsafe = (w0 >= 2) && (w0 + 6 <= W);
    const float* inb  = in  + (size_t)b * 3 * HW;
    const float* in0b = in0 + (size_t)b * 3 * HW;

    // ---- effective 5x5 conv on input (3 channels) ----
#pragma unroll 1
    for (int c = 0; c < 3; c++) {
        const float* inc = inb + c * HW;
#pragma unroll 1
        for (int u = 0; u < 5; u++) {
            int r = h + u - 2;
            float v8[8];
            load8(inc + r * W, w0, (r >= 0 && r < H), colsafe, v8);
            const float* wp = &sW[(c * 5 + u) * 45];
#pragma unroll
            for (int v = 0; v < 5; v++) {
#pragma unroll
                for (int k = 0; k < 9; k++) {
                    float wg = wp[v * 9 + k];
#pragma unroll
                    for (int p = 0; p < 4; p++)
                        acc[k][p] = fmaf(wg, v8[v + p], acc[k][p]);
                }
            }
        }
    }

    // ---- 3x3 conv on input0 (replaced channels 4..6) ----
#pragma unroll 1
    for (int j = 0; j < 3; j++) {
        const float* inc = in0b + j * HW;
#pragma unroll 1
        for (int u = 0; u < 3; u++) {
            int r = h + u - 1;
            float v8[8];
            load8(inc + r * W, w0, (r >= 0 && r < H), colsafe, v8);
            const float* wp = &s0[(j * 3 + u) * 27];
#pragma unroll
            for (int v = 0; v < 3; v++) {
#pragma unroll
                for (int k = 0; k < 9; k++) {
                    float wg = wp[v * 9 + k];
#pragma unroll
                    for (int p = 0; p < 4; p++)
                        acc[k][p] = fmaf(wg, v8[1 + v + p], acc[k][p]);
                }
            }
        }
    }

    // ---- epilogue: per-pixel dot with kernel, plus BN shift ----
    float r0 = 0.f, r1 = 0.f, r2 = 0.f, r3 = 0.f;
    const float* kp = ker + (size_t)b * 9 * HW + h * W + w0;
#pragma unroll
    for (int k = 0; k < 9; k++) {
        float4 kv = *(const float4*)(kp + k * HW);
        float sh = sS[k];
        r0 = fmaf(kv.x, acc[k][0] + sh, r0);
        r1 = fmaf(kv.y, acc[k][1] + sh, r1);
        r2 = fmaf(kv.z, acc[k][2] + sh, r2);
        r3 = fmaf(kv.w, acc[k][3] + sh, r3);
    }
    *(float4*)(out + (size_t)b * HW + h * W + w0) = make_float4(r0, r1, r2, r3);
}

// ---------------------------------------------------------------------------
// Kernel 3: exact path for the 1-pixel ring (double zero-pad semantics).
// Overwrites the ring outputs written (incorrectly) by cspn_main.
// ---------------------------------------------------------------------------
__global__ void border_kernel(const float* __restrict__ ker,
                              const float* __restrict__ in,
                              const float* __restrict__ in0,
                              const float* __restrict__ cw,
                              const float* __restrict__ gam,
                              const float* __restrict__ bet,
                              const float* __restrict__ mu,
                              const float* __restrict__ var,
                              float* __restrict__ out, int total) {
    __shared__ float sw[2187];
    for (int i = threadIdx.x; i < 2187; i += blockDim.x) sw[i] = cw[i];
    __syncthreads();

    int gid = blockIdx.x * blockDim.x + threadIdx.x;
    if (gid >= total) return;

    const int RING = 4 * W - 4;  // 2044
    int b = gid / RING, pos = gid % RING;
    int h, w;
    if (pos < W)            { h = 0;       w = pos; }
    else if (pos < 2 * W)   { h = H - 1;   w = pos - W; }
    else {
        int p2 = pos - 2 * W;
        h = 1 + (p2 >> 1);
        w = (p2 & 1) ? (W - 1) : 0;
    }

    float acc[9];
#pragma unroll
    for (int k = 0; k < 9; k++) acc[k] = 0.f;

    const float* inb  = in  + (size_t)b * 3 * HW;
    const float* in0b = in0 + (size_t)b * 3 * HW;

#pragma unroll 1
    for (int dy = -1; dy <= 1; dy++) {
#pragma unroll 1
        for (int dx = -1; dx <= 1; dx++) {
            int qy = h + dy, qx = w + dx;
            if (qy < 0 || qy >= H || qx < 0 || qx >= W) continue;  // x zero-pad
            int didx = (dy + 1) * 3 + (dx + 1);
#pragma unroll 1
            for (int ch = 0; ch < 27; ch++) {
                float val;
                if (ch >= 4 && ch <= 6) {
                    val = in0b[(ch - 4) * HW + qy * W + qx];
                } else {
                    int c = ch / 9, t = ch % 9;
                    int py = qy + t / 3 - 1, px = qx + t % 3 - 1;
                    val = (py >= 0 && py < H && px >= 0 && px < W)
                              ? inb[c * HW + py * W + px] : 0.f;
                }
#pragma unroll
                for (int k = 0; k < 9; k++)
                    acc[k] = fmaf(sw[(k * 27 + ch) * 9 + didx], val, acc[k]);
            }
        }
    }

    float r = 0.f;
#pragma unroll
    for (int k = 0; k < 9; k++) {
        float s  = gam[k] * rsqrtf(var[k] + BN_EPS);
        float sh = bet[k] - mu[k] * s;
        r = fmaf(ker[((size_t)b * 9 + k) * HW + h * W + w], fmaf(s, acc[k], sh), r);
    }
    out[(size_t)b * HW + h * W + w] = r;
}

// ---------------------------------------------------------------------------
extern "C" void kernel_launch(void* const* d_in, const int* in_sizes, int n_in,
                              void* d_out, int out_size) {
    const float* ker = (const float*)d_in[0];
    const float* in  = (const float*)d_in[1];
    const float* in0 = (const float*)d_in[2];
    const float* cw  = (const float*)d_in[3];
    const float* gam = (const float*)d_in[4];
    const float* bet = (const float*)d_in[5];
    const float* mu  = (const float*)d_in[6];
    const float* var = (const float*)d_in[7];
    float* out = (float*)d_out;

    int bs = in_sizes[0] / (9 * HW);   // batch from kernel tensor size

    prep_kernel<<<1, 1024>>>(cw, gam, bet, mu, var);

    dim3 blk(8, 16);
    dim3 grd(W / 32, H / 16, bs);
    cspn_main<<<grd, blk>>>(ker, in, in0, out);

    int ring_total = bs * (4 * W - 4);
    int nb = (ring_total + 127) / 128;
    border_kernel<<<nb, 128>>>(ker, in, in0, cw, gam, bet, mu, var, out, ring_total);
}